// round 12
// baseline (speedup 1.0000x reference)
#include <cuda_runtime.h>
#include <cstdint>
#include <cstddef>

#define BATCH 4
#define TT    2048
#define CC    1024
#define NEG_INF (__int_as_float(0xff800000))

#define BM 128
#define BN 128
#define BK 32
#define NTH 256

// SMEM: 4 int8 tiles of 128 rows x 48B (32 data + 16 pad), 2 stages
#define ROWB   48
#define TILEB  (128 * ROWB)                // 6144 B
#define OFF_AH 0
#define OFF_AL (1 * TILEB)
#define OFF_BH (2 * TILEB)
#define OFF_BL (3 * TILEB)
#define STAGEB (4 * TILEB)                 // 24576 B
#define SMEM_BYTES (2 * STAGEB)            // 49152 B

#define QMAX 16256.0f                      // 127*128
#define INVQ (1.0f / 16256.0f)

// ---------------- scratch (device globals; allocation-free rule) ------------
#define NQ ((size_t)BATCH * TT * CC)       // 8M elements
__device__ int8_t g_qhi[NQ],  g_qlo[NQ];   __device__ float g_qs [BATCH*TT];
__device__ int8_t g_khi[NQ],  g_klo[NQ];   __device__ float g_ks [BATCH*TT];
__device__ int8_t g_vhi[NQ],  g_vlo[NQ];   __device__ float g_vs [BATCH*TT];
__device__ int8_t g_Wqhi[CC*CC], g_Wqlo[CC*CC]; __device__ float g_Wqs[CC];
__device__ int8_t g_Wkhi[CC*CC], g_Wklo[CC*CC]; __device__ float g_Wks[CC];
__device__ int8_t g_Wvhi[CC*CC], g_Wvlo[CC*CC]; __device__ float g_Wvs[CC];
__device__ int8_t g_Wfhi[CC*CC], g_Wflo[CC*CC]; __device__ float g_Wfs[CC];
__device__ float  g_Qp[NQ], g_Kp[NQ], g_VT[NQ], g_O[NQ];
__device__ int8_t g_Qphi[NQ], g_Qplo[NQ]; __device__ float g_Qps[BATCH*TT];
__device__ int8_t g_Kphi[NQ], g_Kplo[NQ]; __device__ float g_Kps[BATCH*TT];
__device__ int8_t g_VThi[NQ], g_VTlo[NQ]; __device__ float g_VTs[BATCH*CC];
__device__ int8_t g_Ohi[NQ],  g_Olo[NQ];  __device__ float g_Os [BATCH*TT];
__device__ int8_t g_Ehi[(size_t)BATCH*TT*TT], g_Elo[(size_t)BATCH*TT*TT];
__device__ float  g_Es[BATCH*TT];
__device__ float  g_S[(size_t)BATCH*TT*TT];

// ---------------------------------------------------------------------------
__device__ __forceinline__ void mma_s8(int* d, const uint32_t* a, uint32_t b0, uint32_t b1) {
    asm volatile(
        "mma.sync.aligned.m16n8k32.row.col.s32.s8.s8.s32 "
        "{%0,%1,%2,%3},{%4,%5,%6,%7},{%8,%9},{%0,%1,%2,%3};\n"
        : "+r"(d[0]), "+r"(d[1]), "+r"(d[2]), "+r"(d[3])
        : "r"(a[0]), "r"(a[1]), "r"(a[2]), "r"(a[3]), "r"(b0), "r"(b1));
}

#define LDSM4(r, addr)                                                           \
    asm volatile("ldmatrix.sync.aligned.m8n8.x4.shared.b16 {%0,%1,%2,%3}, [%4];" \
        : "=r"((r)[0]), "=r"((r)[1]), "=r"((r)[2]), "=r"((r)[3]) : "r"(addr))

#define CP16(dst_u32, src_ptr) \
    asm volatile("cp.async.cg.shared.global [%0], [%1], 16;" :: "r"(dst_u32), "l"(src_ptr))
#define CP_COMMIT() asm volatile("cp.async.commit_group;")
#define CP_WAIT1()  asm volatile("cp.async.wait_group 1;")

// quantize one fp32 (already scaled by invs) into int8 hi/lo
__device__ __forceinline__ void quant1(float r, int8_t& h, int8_t& l) {
    float hf = rintf(r * 0.0078125f);          // r/128
    float lf = rintf(fmaf(-128.0f, hf, r));
    h = (int8_t)(int)hf;
    l = (int8_t)(int)lf;
}

// ---------------------------------------------------------------------------
// Row-wise two-level int8 quantization: in[row] -> hi/lo + scale.
// rowlen in {1024, 2048}; one block per row.
// ---------------------------------------------------------------------------
__device__ __forceinline__ void rowquant_body(
    const float* __restrict__ in, int8_t* __restrict__ hi,
    int8_t* __restrict__ lo, float* __restrict__ sc, int rowlen, int row)
{
    const size_t base = (size_t)row * rowlen;
    const int t = threadIdx.x, lane = t & 31, wp = t >> 5;
    __shared__ float red[8];

    float v[8];
    const int nv = rowlen >> 8;                // 4 or 8
    float mx = 0.0f;
    for (int i = 0; i < nv; i++) {
        v[i] = in[base + t + (i << 8)];
        mx = fmaxf(mx, fabsf(v[i]));
    }
#pragma unroll
    for (int s = 16; s > 0; s >>= 1) mx = fmaxf(mx, __shfl_xor_sync(~0u, mx, s));
    if (lane == 0) red[wp] = mx;
    __syncthreads();
    mx = red[0];
#pragma unroll
    for (int i = 1; i < 8; i++) mx = fmaxf(mx, red[i]);

    const float invs = (mx > 0.0f) ? (QMAX / mx) : 0.0f;
    if (t == 0) sc[row] = mx * INVQ;
    for (int i = 0; i < nv; i++) {
        int8_t h, l;
        quant1(v[i] * invs, h, l);
        hi[base + t + (i << 8)] = h;
        lo[base + t + (i << 8)] = l;
    }
}

__global__ __launch_bounds__(256)
void rowquant(const float* __restrict__ in, int8_t* __restrict__ hi,
              int8_t* __restrict__ lo, float* __restrict__ sc, int rowlen)
{
    rowquant_body(in, hi, lo, sc, rowlen, blockIdx.x);
}

// fused prepass: 7 input tensors, all rowlen=1024; y selects; guard rows.
__global__ __launch_bounds__(256)
void rowquant_pre(const float* __restrict__ q, const float* __restrict__ k,
                  const float* __restrict__ v, const float* __restrict__ Wq,
                  const float* __restrict__ Wk, const float* __restrict__ Wv,
                  const float* __restrict__ Wf,
                  int8_t* qh, int8_t* ql, float* qs,
                  int8_t* kh, int8_t* kl, float* ks,
                  int8_t* vh, int8_t* vl, float* vs,
                  int8_t* Wqh, int8_t* Wql, float* Wqs,
                  int8_t* Wkh, int8_t* Wkl, float* Wks,
                  int8_t* Wvh, int8_t* Wvl, float* Wvs,
                  int8_t* Wfh, int8_t* Wfl, float* Wfs)
{
    const int s = blockIdx.y, row = blockIdx.x;
    if (s >= 3 && row >= CC) return;
    const float* in; int8_t *hi, *lo; float* sc;
    switch (s) {
        case 0: in = q;  hi = qh;  lo = ql;  sc = qs;  break;
        case 1: in = k;  hi = kh;  lo = kl;  sc = ks;  break;
        case 2: in = v;  hi = vh;  lo = vl;  sc = vs;  break;
        case 3: in = Wq; hi = Wqh; lo = Wql; sc = Wqs; break;
        case 4: in = Wk; hi = Wkh; lo = Wkl; sc = Wks; break;
        case 5: in = Wv; hi = Wvh; lo = Wvl; sc = Wvs; break;
        default: in = Wf; hi = Wfh; lo = Wfl; sc = Wfs; break;
    }
    rowquant_body(in, hi, lo, sc, CC, row);
}

// ---------------------------------------------------------------------------
// Core two-level int8 IMMA GEMM-NT tile.
//   C[m,n] = alpha*sa[m]*sb[n]*(16384*Hh + 128*Cross) (+bias) (+mask)
// ---------------------------------------------------------------------------
__device__ __forceinline__ void gemm_core_i8(
    const int8_t* __restrict__ Ahi, const int8_t* __restrict__ Alo,
    const float* __restrict__ As,
    const int8_t* __restrict__ Bhi, const int8_t* __restrict__ Blo,
    const float* __restrict__ Bs,
    const float* __restrict__ bias, float* __restrict__ Cf,
    int N, int K, int m0, int n0, int Keff,
    float alpha, int diag, int transC)
{
    const int nch = Keff / BK;

    extern __shared__ char sm[];
    const uint32_t smb = (uint32_t)__cvta_generic_to_shared(sm);

    const int t = threadIdx.x, w = t >> 5, lane = t & 31;
    const int qr = lane >> 2, qc = (lane & 3) * 2;
    const int mb = (w & 1) * 64, nb = (w >> 1) * 32;

    // cp.async: one 16B half-row per tile per thread
    const int lr = t >> 1, lh = (t & 1) * 16;
    const int8_t* pAh = Ahi + (size_t)(m0 + lr) * K + lh;
    const int8_t* pAl = Alo + (size_t)(m0 + lr) * K + lh;
    const int8_t* pBh = Bhi + (size_t)(n0 + lr) * K + lh;
    const int8_t* pBl = Blo + (size_t)(n0 + lr) * K + lh;
    const uint32_t dA = (uint32_t)(lr * ROWB + lh);

    // ldmatrix byte offsets
    uint32_t offA[4];
#pragma unroll
    for (int ii = 0; ii < 4; ii++)
        offA[ii] = (uint32_t)((mb + ii * 16 + (lane & 15)) * ROWB + (lane >> 4) * 16);
    uint32_t offB[2];
#pragma unroll
    for (int jp = 0; jp < 2; jp++)
        offB[jp] = (uint32_t)((nb + jp * 16 + ((lane >> 4) & 1) * 8 + (lane & 7)) * ROWB
                              + ((lane >> 3) & 1) * 16);

    int accH[4][4][4] = {};
    int accC[4][4][4] = {};

    auto issue = [&](int i) {
        const int k0 = i * BK;
        const uint32_t stg = smb + (uint32_t)((i & 1) * STAGEB);
        CP16(stg + OFF_AH + dA, pAh + k0);
        CP16(stg + OFF_AL + dA, pAl + k0);
        CP16(stg + OFF_BH + dA, pBh + k0);
        CP16(stg + OFF_BL + dA, pBl + k0);
        CP_COMMIT();
    };

    issue(0);
    if (nch > 1) issue(1);

#define BH0(j) bh[(j) >> 1][((j) & 1) * 2]
#define BH1(j) bh[(j) >> 1][((j) & 1) * 2 + 1]
#define BL0(j) bl[(j) >> 1][((j) & 1) * 2]
#define BL1(j) bl[(j) >> 1][((j) & 1) * 2 + 1]

    for (int i = 0; i < nch; i++) {
        CP_WAIT1();
        __syncthreads();
        const uint32_t stg = smb + (uint32_t)((i & 1) * STAGEB);
        uint32_t bh[2][4], bl[2][4];
        LDSM4(bh[0], stg + OFF_BH + offB[0]);
        LDSM4(bh[1], stg + OFF_BH + offB[1]);
        LDSM4(bl[0], stg + OFF_BL + offB[0]);
        LDSM4(bl[1], stg + OFF_BL + offB[1]);
#pragma unroll
        for (int ip = 0; ip < 2; ip++) {
            const int i0 = ip * 2, i1 = ip * 2 + 1;
            uint32_t ah0[4], al0[4], ah1[4], al1[4];
            LDSM4(ah0, stg + OFF_AH + offA[i0]);
            LDSM4(al0, stg + OFF_AL + offA[i0]);
            LDSM4(ah1, stg + OFF_AH + offA[i1]);
            LDSM4(al1, stg + OFF_AL + offA[i1]);
            // hi*hi -> accH ; hi*lo + lo*hi -> accC (dep distance >= 8)
#pragma unroll
            for (int j = 0; j < 4; j++) mma_s8(accH[i0][j], ah0, BH0(j), BH1(j));
#pragma unroll
            for (int j = 0; j < 4; j++) mma_s8(accH[i1][j], ah1, BH0(j), BH1(j));
#pragma unroll
            for (int j = 0; j < 4; j++) mma_s8(accC[i0][j], ah0, BL0(j), BL1(j));
#pragma unroll
            for (int j = 0; j < 4; j++) mma_s8(accC[i1][j], ah1, BL0(j), BL1(j));
#pragma unroll
            for (int j = 0; j < 4; j++) mma_s8(accC[i0][j], al0, BH0(j), BH1(j));
#pragma unroll
            for (int j = 0; j < 4; j++) mma_s8(accC[i1][j], al1, BH0(j), BH1(j));
        }
        __syncthreads();
        if (i + 2 < nch) issue(i + 2);
    }

#undef BH0
#undef BH1
#undef BL0
#undef BL1

    // ---- epilogue: combine two accumulators with row/col scales
#pragma unroll
    for (int ii = 0; ii < 4; ii++) {
        const int rA = m0 + mb + ii * 16 + qr;
        const int rB = rA + 8;
        const float saA = As[rA] * alpha, saB = As[rB] * alpha;
#pragma unroll
        for (int j = 0; j < 4; j++) {
            const int cb = n0 + nb + j * 8 + qc;
            const float sb0 = Bs[cb], sb1 = Bs[cb + 1];
            float v00 = fmaf(16384.0f, (float)accH[ii][j][0], 128.0f * (float)accC[ii][j][0]) * saA * sb0;
            float v01 = fmaf(16384.0f, (float)accH[ii][j][1], 128.0f * (float)accC[ii][j][1]) * saA * sb1;
            float v10 = fmaf(16384.0f, (float)accH[ii][j][2], 128.0f * (float)accC[ii][j][2]) * saB * sb0;
            float v11 = fmaf(16384.0f, (float)accH[ii][j][3], 128.0f * (float)accC[ii][j][3]) * saB * sb1;
            if (bias) {
                const float b0 = bias[cb], b1 = bias[cb + 1];
                v00 += b0; v01 += b1; v10 += b0; v11 += b1;
            }
            if (diag) {
                if (cb     > rA) v00 = NEG_INF;
                if (cb + 1 > rA) v01 = NEG_INF;
                if (cb     > rB) v10 = NEG_INF;
                if (cb + 1 > rB) v11 = NEG_INF;
            }
            if (transC) {
                const size_t bo = (size_t)(rA >> 11) * ((size_t)CC * TT);
                const int mA = rA & (TT - 1), mB = rB & (TT - 1);
                Cf[bo + (size_t)cb       * TT + mA] = v00;
                Cf[bo + (size_t)(cb + 1) * TT + mA] = v01;
                Cf[bo + (size_t)cb       * TT + mB] = v10;
                Cf[bo + (size_t)(cb + 1) * TT + mB] = v11;
            } else {
                *(float2*)&Cf[(size_t)rA * N + cb] = make_float2(v00, v01);
                *(float2*)&Cf[(size_t)rB * N + cb] = make_float2(v10, v11);
            }
        }
    }
}

// ---------------------------------------------------------------------------
// Fused Q/K/V projection (z selects problem; V output transposed fp32)
// ---------------------------------------------------------------------------
__global__ __launch_bounds__(NTH, 1)
void gemm_qkv_i8(const int8_t* qh, const int8_t* ql, const float* qs,
                 const int8_t* kh, const int8_t* kl, const float* ks,
                 const int8_t* vh, const int8_t* vl, const float* vs,
                 const int8_t* Wqh, const int8_t* Wql, const float* Wqs,
                 const int8_t* Wkh, const int8_t* Wkl, const float* Wks,
                 const int8_t* Wvh, const int8_t* Wvl, const float* Wvs,
                 const float* bq, const float* bk, const float* bv,
                 float* Qp, float* Kp, float* VT)
{
    const int z = blockIdx.z;
    const int8_t *Ah, *Al, *Bh, *Bl;
    const float *As, *Bs, *bias;
    float* Cf;
    int transC = 0;
    if (z == 0)      { Ah=qh; Al=ql; As=qs; Bh=Wqh; Bl=Wql; Bs=Wqs; bias=bq; Cf=Qp; }
    else if (z == 1) { Ah=kh; Al=kl; As=ks; Bh=Wkh; Bl=Wkl; Bs=Wks; bias=bk; Cf=Kp; }
    else             { Ah=vh; Al=vl; As=vs; Bh=Wvh; Bl=Wvl; Bs=Wvs; bias=bv; Cf=VT; transC=1; }
    gemm_core_i8(Ah, Al, As, Bh, Bl, Bs, bias, Cf,
                 CC, CC, blockIdx.y * BM, blockIdx.x * BN, CC, 1.0f, 0, transC);
}

// ---------------------------------------------------------------------------
// General int8 GEMM (scores / E@V / final projection)
// ---------------------------------------------------------------------------
__global__ __launch_bounds__(NTH, 1)
void gemm_i8(const int8_t* __restrict__ Ahi, const int8_t* __restrict__ Alo,
             const float* __restrict__ As,
             const int8_t* __restrict__ Bhi, const int8_t* __restrict__ Blo,
             const float* __restrict__ Bs,
             const float* __restrict__ bias, float* __restrict__ Cf,
             int N, int K,
             size_t sA, size_t sB, size_t sC, int sAs, int sBs,
             float alpha, int causal, int kvlim, int transC)
{
    const int bx = blockIdx.x, by = blockIdx.y, bz = blockIdx.z;
    if (causal && bx > by) return;
    const int Keff = kvlim ? (by + 1) * BM : K;
    gemm_core_i8(Ahi + (size_t)bz * sA, Alo + (size_t)bz * sA, As + bz * sAs,
                 Bhi + (size_t)bz * sB, Blo + (size_t)bz * sB, Bs + bz * sBs,
                 bias, Cf + (size_t)bz * sC,
                 N, K, by * BM, bx * BN, Keff,
                 alpha, causal && bx == by, transC);
}

// ---------------------------------------------------------------------------
// Softmax: S fp32 -> quantized exp (Ehi/Elo int8, fixed scale 1/16256) and
// per-row output scale Es = (1/sum)/16256.
// ---------------------------------------------------------------------------
__global__ __launch_bounds__(256)
void softmax_q_kernel(const float* __restrict__ S, int8_t* __restrict__ Ehi,
                      int8_t* __restrict__ Elo, float* __restrict__ Es)
{
    const int row = blockIdx.x;
    const int b   = blockIdx.y;
    const size_t base = ((size_t)b * TT + row) * TT;
    const float* Sr = S + base;
    const int ncols = ((row >> 7) + 1) << 7;
    const int t = threadIdx.x;
    const int lane = t & 31, wp = t >> 5;

    __shared__ float red[8];

    float vals[8];
    float mx = NEG_INF;
#pragma unroll
    for (int i = 0; i < 8; i++) {
        const int c = t + i * 256;
        vals[i] = (c < ncols) ? Sr[c] : NEG_INF;
        mx = fmaxf(mx, vals[i]);
    }
#pragma unroll
    for (int s = 16; s > 0; s >>= 1) mx = fmaxf(mx, __shfl_xor_sync(~0u, mx, s));
    if (lane == 0) red[wp] = mx;
    __syncthreads();
    mx = red[0];
#pragma unroll
    for (int i = 1; i < 8; i++) mx = fmaxf(mx, red[i]);

    float sum = 0.0f;
#pragma unroll
    for (int i = 0; i < 8; i++) {
        vals[i] = __expf(vals[i] - mx);   // max value is exactly 1
        sum += vals[i];
    }
#pragma unroll
    for (int s = 16; s > 0; s >>= 1) sum += __shfl_xor_sync(~0u, sum, s);
    __syncthreads();
    if (lane == 0) red[wp] = sum;
    __syncthreads();
    sum = 0.0f;
#pragma unroll
    for (int i = 0; i < 8; i++) sum += red[i];

    if (t == 0) Es[b * TT + row] = (1.0f / sum) * INVQ;

#pragma unroll
    for (int i = 0; i < 8; i++) {
        const int c = t + i * 256;
        if (c < ncols) {
            int8_t h, l;
            quant1(vals[i] * QMAX, h, l);
            Ehi[base + c] = h;
            Elo[base + c] = l;
        }
    }
}

// ---------------------------------------------------------------------------
extern "C" void kernel_launch(void* const* d_in, const int* in_sizes, int n_in,
                              void* d_out, int out_size)
{
    const float* q   = (const float*)d_in[0];
    const float* k   = (const float*)d_in[1];
    const float* v   = (const float*)d_in[2];
    const float* Wq  = (const float*)d_in[3];
    const float* bq  = (const float*)d_in[4];
    const float* Wk  = (const float*)d_in[5];
    const float* bk  = (const float*)d_in[6];
    const float* Wv  = (const float*)d_in[7];
    const float* bv  = (const float*)d_in[8];
    const float* Wff = (const float*)d_in[9];
    const float* bff = (const float*)d_in[10];
    float* out = (float*)d_out;

#define SYM(T, p, g) T p; cudaGetSymbolAddress((void**)&p, g)
    SYM(int8_t*, qhi, g_qhi);  SYM(int8_t*, qlo, g_qlo);  SYM(float*, qs, g_qs);
    SYM(int8_t*, khi, g_khi);  SYM(int8_t*, klo, g_klo);  SYM(float*, ks, g_ks);
    SYM(int8_t*, vhi, g_vhi);  SYM(int8_t*, vlo, g_vlo);  SYM(float*, vs, g_vs);
    SYM(int8_t*, Wqhi, g_Wqhi); SYM(int8_t*, Wqlo, g_Wqlo); SYM(float*, Wqs, g_Wqs);
    SYM(int8_t*, Wkhi, g_Wkhi); SYM(int8_t*, Wklo, g_Wklo); SYM(float*, Wks, g_Wks);
    SYM(int8_t*, Wvhi, g_Wvhi); SYM(int8_t*, Wvlo, g_Wvlo); SYM(float*, Wvs, g_Wvs);
    SYM(int8_t*, Wfhi, g_Wfhi); SYM(int8_t*, Wflo, g_Wflo); SYM(float*, Wfs, g_Wfs);
    SYM(float*, Qp, g_Qp); SYM(float*, Kp, g_Kp); SYM(float*, VT, g_VT); SYM(float*, O, g_O);
    SYM(int8_t*, Qphi, g_Qphi); SYM(int8_t*, Qplo, g_Qplo); SYM(float*, Qps, g_Qps);
    SYM(int8_t*, Kphi, g_Kphi); SYM(int8_t*, Kplo, g_Kplo); SYM(float*, Kps, g_Kps);
    SYM(int8_t*, VThi, g_VThi); SYM(int8_t*, VTlo, g_VTlo); SYM(float*, VTs, g_VTs);
    SYM(int8_t*, Ohi, g_Ohi);   SYM(int8_t*, Olo, g_Olo);   SYM(float*, Os, g_Os);
    SYM(int8_t*, Ehi, g_Ehi);   SYM(int8_t*, Elo, g_Elo);   SYM(float*, Es, g_Es);
    SYM(float*, S, g_S);
#undef SYM

    cudaFuncSetAttribute(gemm_qkv_i8, cudaFuncAttributeMaxDynamicSharedMemorySize, SMEM_BYTES);
    cudaFuncSetAttribute(gemm_i8,     cudaFuncAttributeMaxDynamicSharedMemorySize, SMEM_BYTES);

    const int M = BATCH * TT;   // 8192

    // 0) quantize raw inputs (one fused launch)
    rowquant_pre<<<dim3(M, 7), 256>>>(
        q, k, v, Wq, Wk, Wv, Wff,
        qhi, qlo, qs, khi, klo, ks, vhi, vlo, vs,
        Wqhi, Wqlo, Wqs, Wkhi, Wklo, Wks, Wvhi, Wvlo, Wvs, Wfhi, Wflo, Wfs);

    const dim3 blk(NTH);

    // 1) fused Q/K/V projections -> fp32 (V transposed)
    gemm_qkv_i8<<<dim3(CC/BN, M/BM, 3), blk, SMEM_BYTES>>>(
        qhi, qlo, qs, khi, klo, ks, vhi, vlo, vs,
        Wqhi, Wqlo, Wqs, Wkhi, Wklo, Wks, Wvhi, Wvlo, Wvs,
        bq, bk, bv, Qp, Kp, VT);

    // 2) quantize intermediates
    rowquant<<<M, 256>>>(Qp, Qphi, Qplo, Qps, CC);
    rowquant<<<M, 256>>>(Kp, Kphi, Kplo, Kps, CC);
    rowquant<<<BATCH * CC, 256>>>(VT, VThi, VTlo, VTs, TT);

    // 3) Scores -> fp32 S (causal lower-tri blocks only)
    gemm_i8<<<dim3(TT/BN, TT/BM, BATCH), blk, SMEM_BYTES>>>(
        Qphi, Qplo, Qps, Kphi, Kplo, Kps, nullptr, S,
        TT, CC, (size_t)TT*CC, (size_t)TT*CC, (size_t)TT*TT, TT, TT,
        1.0f/32.0f, 1, 0, 0);

    // 4) softmax -> quantized exp + row scales
    softmax_q_kernel<<<dim3(TT, BATCH), dim3(256)>>>(S, Ehi, Elo, Es);

    // 5) O = E @ V (NT vs transposed V, causal K-limit) -> fp32 O
    gemm_i8<<<dim3(CC/BN, TT/BM, BATCH), blk, SMEM_BYTES>>>(
        Ehi, Elo, Es, VThi, VTlo, VTs, nullptr, O,
        CC, TT, (size_t)TT*TT, (size_t)CC*TT, (size_t)TT*CC, TT, CC,
        1.0f, 0, 1, 0);

    // 6) quantize O
    rowquant<<<M, 256>>>(O, Ohi, Olo, Os, CC);

    // 7) final projection -> fp32 out
    gemm_i8<<<dim3(CC/BN, M/BM, 1), blk, SMEM_BYTES>>>(
        Ohi, Olo, Os, Wfhi, Wflo, Wfs, bff, out,
        CC, CC, 0, 0, 0, 0, 0, 1.0f, 0, 0, 0);
}

// round 14
// speedup vs baseline: 2.9114x; 2.9114x over previous
#include <cuda_runtime.h>
#include <cuda_fp16.h>
#include <cstdint>
#include <cstddef>

#define BATCH 4
#define TT    2048
#define CC    1024
#define NEG_INF (__int_as_float(0xff800000))

#define BM 128
#define BN 128
#define BK 32
#define NTH 256

// SMEM: up to 4 fp16 tiles of 128 rows x 40 (32 + 8 pad) per stage, 2 stages
#define ROWSTR 40
#define TILE_E (128 * ROWSTR)
#define OFF_AH 0
#define OFF_AL (1 * TILE_E)
#define OFF_BH (2 * TILE_E)
#define OFF_BL (3 * TILE_E)
#define STAGE_E (4 * TILE_E)               // 20480 elems = 40960 B
#define SMEM_BYTES (2 * STAGE_E * 2)       // 81920 B

typedef __half h16;

// MODE 0: 3-term  (A hi/lo, B hi/lo; AhBh + AhBl + AlBh)
// MODE 1: 2-term A-split (A hi/lo, B single; AhB + AlB)
// MODE 2: 2-term B-split (A single, B hi/lo; ABh + ABl)

// ---------------- scratch (device globals; allocation-free rule) ------------
__device__ h16 g_qh[(size_t)BATCH*TT*CC],  g_ql[(size_t)BATCH*TT*CC];
__device__ h16 g_kh[(size_t)BATCH*TT*CC],  g_kl[(size_t)BATCH*TT*CC];
__device__ h16 g_vh[(size_t)BATCH*TT*CC],  g_vl[(size_t)BATCH*TT*CC];
__device__ h16 g_Wqh[CC*CC], g_Wql[CC*CC];
__device__ h16 g_Wkh[CC*CC], g_Wkl[CC*CC];
__device__ h16 g_Wvh[CC*CC], g_Wvl[CC*CC];
__device__ h16 g_Wfh[CC*CC], g_Wfl[CC*CC];
__device__ h16 g_Qh[(size_t)BATCH*TT*CC],  g_Ql[(size_t)BATCH*TT*CC];
__device__ h16 g_Kh[(size_t)BATCH*TT*CC],  g_Kl[(size_t)BATCH*TT*CC];
__device__ h16 g_VTh[(size_t)BATCH*CC*TT], g_VTl[(size_t)BATCH*CC*TT];
__device__ h16 g_Oh[(size_t)BATCH*TT*CC],  g_Ol[(size_t)BATCH*TT*CC];
__device__ h16 g_Ph[(size_t)BATCH*TT*TT];
__device__ float g_S[(size_t)BATCH*TT*TT];

// ---------------------------------------------------------------------------
__device__ __forceinline__ void mma_f16(float* d, const uint32_t* a, uint32_t b0, uint32_t b1) {
    asm volatile(
        "mma.sync.aligned.m16n8k16.row.col.f32.f16.f16.f32 "
        "{%0,%1,%2,%3},{%4,%5,%6,%7},{%8,%9},{%0,%1,%2,%3};\n"
        : "+f"(d[0]), "+f"(d[1]), "+f"(d[2]), "+f"(d[3])
        : "r"(a[0]), "r"(a[1]), "r"(a[2]), "r"(a[3]), "r"(b0), "r"(b1));
}

#define LDSM4(r, addr)                                                           \
    asm volatile("ldmatrix.sync.aligned.m8n8.x4.shared.b16 {%0,%1,%2,%3}, [%4];" \
        : "=r"((r)[0]), "=r"((r)[1]), "=r"((r)[2]), "=r"((r)[3]) : "r"(addr))

#define CP16(dst_u32, src_ptr) \
    asm volatile("cp.async.cg.shared.global [%0], [%1], 16;" :: "r"(dst_u32), "l"(src_ptr))
#define CP_COMMIT() asm volatile("cp.async.commit_group;")
#define CP_WAIT1()  asm volatile("cp.async.wait_group 1;")

__device__ __forceinline__ void split1(float f, h16& h, h16& l) {
    h = __float2half_rn(f);
    l = __float2half_rn(f - __half2float(h));
}

// ---------------------------------------------------------------------------
// One fused split prepass for all 7 fp32 tensors -> fp16 hi/lo
// ---------------------------------------------------------------------------
__global__ __launch_bounds__(256)
void split_all(const float* __restrict__ q, const float* __restrict__ k,
               const float* __restrict__ v, const float* __restrict__ Wq,
               const float* __restrict__ Wk, const float* __restrict__ Wv,
               const float* __restrict__ Wf,
               h16* __restrict__ qh, h16* __restrict__ ql,
               h16* __restrict__ kh, h16* __restrict__ kl,
               h16* __restrict__ vh, h16* __restrict__ vl,
               h16* __restrict__ Wqh, h16* __restrict__ Wql,
               h16* __restrict__ Wkh, h16* __restrict__ Wkl,
               h16* __restrict__ Wvh, h16* __restrict__ Wvl,
               h16* __restrict__ Wfh, h16* __restrict__ Wfl,
               int nbig4, int nsmall4)
{
    const int s = blockIdx.y;
    const int n4 = (s < 3) ? nbig4 : nsmall4;
    const int i = blockIdx.x * 256 + threadIdx.x;
    if (i >= n4) return;
    const float* src; h16* hi; h16* lo;
    switch (s) {
        case 0: src = q;  hi = qh;  lo = ql;  break;
        case 1: src = k;  hi = kh;  lo = kl;  break;
        case 2: src = v;  hi = vh;  lo = vl;  break;
        case 3: src = Wq; hi = Wqh; lo = Wql; break;
        case 4: src = Wk; hi = Wkh; lo = Wkl; break;
        case 5: src = Wv; hi = Wvh; lo = Wvl; break;
        default: src = Wf; hi = Wfh; lo = Wfl; break;
    }
    float4 f = ((const float4*)src)[i];
    h16 h0,l0,h1,l1,h2,l2,h3,l3;
    split1(f.x,h0,l0); split1(f.y,h1,l1); split1(f.z,h2,l2); split1(f.w,h3,l3);
    ((__half2*)hi)[2*i]   = __half2{h0,h1};
    ((__half2*)hi)[2*i+1] = __half2{h2,h3};
    ((__half2*)lo)[2*i]   = __half2{l0,l1};
    ((__half2*)lo)[2*i+1] = __half2{l2,l3};
}

// ---------------------------------------------------------------------------
// Core split-fp16 mma.sync GEMM-NT tile, MODE-templated term structure.
// ---------------------------------------------------------------------------
template<int MODE>
__device__ __forceinline__ void gemm_core(
    const h16* __restrict__ Ah, const h16* __restrict__ Al,
    const h16* __restrict__ Bh, const h16* __restrict__ Bl,
    const float* __restrict__ bias,
    float* __restrict__ Cf, h16* __restrict__ Ch, h16* __restrict__ Cl,
    int N, int K, int m0, int n0, int Keff,
    float alpha, int diag, int transC)
{
    const int nch = Keff / BK;

    extern __shared__ h16 sm[];
    const uint32_t smb = (uint32_t)__cvta_generic_to_shared(sm);

    const int t = threadIdx.x, w = t >> 5, lane = t & 31;
    const int qr = lane >> 2, qc = (lane & 3) * 2;
    const int mb = (w & 1) * 64, nb = (w >> 1) * 32;

    // cp.async geometry: 2 16B-chunks per tile per thread (same row, adjacent cols)
    const int r0 = (t * 2) >> 2, c0 = (t * 2) & 3;

    const h16* pAh = Ah + (size_t)(m0 + r0) * K + c0 * 8;
    const h16* pAl = Al + (size_t)(m0 + r0) * K + c0 * 8;
    const h16* pBh = Bh + (size_t)(n0 + r0) * K + c0 * 8;
    const h16* pBl = Bl + (size_t)(n0 + r0) * K + c0 * 8;
    const uint32_t dA0 = (uint32_t)((r0 * ROWSTR + c0 * 8) * 2);
    const uint32_t dA1 = dA0 + 16;

    // ldmatrix per-lane byte offsets
    uint32_t offA[4];
#pragma unroll
    for (int ii = 0; ii < 4; ii++)
        offA[ii] = (uint32_t)(((mb + ii * 16 + (lane & 15)) * ROWSTR + (lane >> 4) * 8) * 2);
    uint32_t offB[2];
#pragma unroll
    for (int jp = 0; jp < 2; jp++)
        offB[jp] = (uint32_t)(((nb + jp * 16 + ((lane >> 4) * 8) + (lane & 7)) * ROWSTR
                               + ((lane >> 3) & 1) * 8) * 2);

    float acc[4][4][4] = {};

    auto issue = [&](int i) {
        const int k0 = i * BK;
        const uint32_t stg = smb + (uint32_t)((i & 1) * STAGE_E * 2);
        CP16(stg + OFF_AH*2 + dA0, pAh + k0);
        CP16(stg + OFF_AH*2 + dA1, pAh + k0 + 8);
        if (MODE != 2) {
            CP16(stg + OFF_AL*2 + dA0, pAl + k0);
            CP16(stg + OFF_AL*2 + dA1, pAl + k0 + 8);
        }
        CP16(stg + OFF_BH*2 + dA0, pBh + k0);
        CP16(stg + OFF_BH*2 + dA1, pBh + k0 + 8);
        if (MODE != 1) {
            CP16(stg + OFF_BL*2 + dA0, pBl + k0);
            CP16(stg + OFF_BL*2 + dA1, pBl + k0 + 8);
        }
        CP_COMMIT();
    };

    issue(0);
    if (nch > 1) issue(1);

#define BH0(j) bh[(j) >> 1][((j) & 1) * 2]
#define BH1(j) bh[(j) >> 1][((j) & 1) * 2 + 1]
#define BL0(j) bl[(j) >> 1][((j) & 1) * 2]
#define BL1(j) bl[(j) >> 1][((j) & 1) * 2 + 1]

    for (int i = 0; i < nch; i++) {
        CP_WAIT1();
        __syncthreads();
        const uint32_t stg = smb + (uint32_t)((i & 1) * STAGE_E * 2);
#pragma unroll
        for (int kk = 0; kk < BK; kk += 16) {
            const uint32_t kkb = (uint32_t)(kk * 2);
            uint32_t bh[2][4], bl[2][4];
            LDSM4(bh[0], stg + OFF_BH*2 + offB[0] + kkb);
            LDSM4(bh[1], stg + OFF_BH*2 + offB[1] + kkb);
            if (MODE != 1) {
                LDSM4(bl[0], stg + OFF_BL*2 + offB[0] + kkb);
                LDSM4(bl[1], stg + OFF_BL*2 + offB[1] + kkb);
            }
#pragma unroll
            for (int ip = 0; ip < 2; ip++) {
                const int i0 = ip * 2, i1 = ip * 2 + 1;
                uint32_t ah0[4], al0[4], ah1[4], al1[4];
                LDSM4(ah0, stg + OFF_AH*2 + offA[i0] + kkb);
                LDSM4(ah1, stg + OFF_AH*2 + offA[i1] + kkb);
                if (MODE != 2) {
                    LDSM4(al0, stg + OFF_AL*2 + offA[i0] + kkb);
                    LDSM4(al1, stg + OFF_AL*2 + offA[i1] + kkb);
                }
#pragma unroll
                for (int j = 0; j < 4; j++) mma_f16(acc[i0][j], ah0, BH0(j), BH1(j));
#pragma unroll
                for (int j = 0; j < 4; j++) mma_f16(acc[i1][j], ah1, BH0(j), BH1(j));
                if (MODE != 1) {
#pragma unroll
                    for (int j = 0; j < 4; j++) mma_f16(acc[i0][j], ah0, BL0(j), BL1(j));
#pragma unroll
                    for (int j = 0; j < 4; j++) mma_f16(acc[i1][j], ah1, BL0(j), BL1(j));
                }
                if (MODE != 2) {
#pragma unroll
                    for (int j = 0; j < 4; j++) mma_f16(acc[i0][j], al0, BH0(j), BH1(j));
#pragma unroll
                    for (int j = 0; j < 4; j++) mma_f16(acc[i1][j], al1, BH0(j), BH1(j));
                }
            }
        }
        __syncthreads();
        if (i + 2 < nch) issue(i + 2);
    }

#undef BH0
#undef BH1
#undef BL0
#undef BL1

    // ---- epilogue
#pragma unroll
    for (int ii = 0; ii < 4; ii++) {
#pragma unroll
        for (int j = 0; j < 4; j++) {
            const int rA = m0 + mb + ii * 16 + qr;
            const int rB = rA + 8;
            const int cb = n0 + nb + j * 8 + qc;
            float v00 = acc[ii][j][0] * alpha, v01 = acc[ii][j][1] * alpha;
            float v10 = acc[ii][j][2] * alpha, v11 = acc[ii][j][3] * alpha;
            if (bias) {
                const float b0 = bias[cb], b1 = bias[cb + 1];
                v00 += b0; v01 += b1; v10 += b0; v11 += b1;
            }
            if (diag) {
                if (cb     > rA) v00 = NEG_INF;
                if (cb + 1 > rA) v01 = NEG_INF;
                if (cb     > rB) v10 = NEG_INF;
                if (cb + 1 > rB) v11 = NEG_INF;
            }
            if (Cf) {
                *(float2*)&Cf[(size_t)rA * N + cb] = make_float2(v00, v01);
                *(float2*)&Cf[(size_t)rB * N + cb] = make_float2(v10, v11);
            } else if (transC) {
                const size_t bo = (size_t)(rA >> 11) * ((size_t)CC * TT);
                const int mA = rA & (TT - 1), mB = rB & (TT - 1);
                h16 h, l;
                split1(v00, h, l); Ch[bo + (size_t)cb*TT + mA] = h; Cl[bo + (size_t)cb*TT + mA] = l;
                split1(v01, h, l); Ch[bo + (size_t)(cb+1)*TT + mA] = h; Cl[bo + (size_t)(cb+1)*TT + mA] = l;
                split1(v10, h, l); Ch[bo + (size_t)cb*TT + mB] = h; Cl[bo + (size_t)cb*TT + mB] = l;
                split1(v11, h, l); Ch[bo + (size_t)(cb+1)*TT + mB] = h; Cl[bo + (size_t)(cb+1)*TT + mB] = l;
            } else {
                h16 h0,l0,h1,l1;
                split1(v00,h0,l0); split1(v01,h1,l1);
                *(__half2*)&Ch[(size_t)rA*N + cb] = __half2{h0,h1};
                *(__half2*)&Cl[(size_t)rA*N + cb] = __half2{l0,l1};
                split1(v10,h0,l0); split1(v11,h1,l1);
                *(__half2*)&Ch[(size_t)rB*N + cb] = __half2{h0,h1};
                *(__half2*)&Cl[(size_t)rB*N + cb] = __half2{l0,l1};
            }
        }
    }
}

// ---------------------------------------------------------------------------
// Fused Q/K projection (3-term): z selects problem.
// ---------------------------------------------------------------------------
__global__ __launch_bounds__(NTH, 2)
void gemm_qk(const h16* __restrict__ qh, const h16* __restrict__ ql,
             const h16* __restrict__ kh, const h16* __restrict__ kl,
             const h16* __restrict__ Wqh, const h16* __restrict__ Wql,
             const h16* __restrict__ Wkh, const h16* __restrict__ Wkl,
             const float* __restrict__ bq, const float* __restrict__ bk,
             h16* __restrict__ Qh, h16* __restrict__ Ql,
             h16* __restrict__ Kh, h16* __restrict__ Kl)
{
    const int z = blockIdx.z;
    gemm_core<0>(z ? kh : qh, z ? kl : ql, z ? Wkh : Wqh, z ? Wkl : Wql,
                 z ? bk : bq, nullptr, z ? Kh : Qh, z ? Kl : Ql,
                 CC, CC, blockIdx.y * BM, blockIdx.x * BN, CC, 1.0f, 0, 0);
}

// ---------------------------------------------------------------------------
// V projection (2-term A-split), output transposed per batch.
// ---------------------------------------------------------------------------
__global__ __launch_bounds__(NTH, 2)
void gemm_v(const h16* __restrict__ vh, const h16* __restrict__ vl,
            const h16* __restrict__ Wvh,
            const float* __restrict__ bv,
            h16* __restrict__ VTh, h16* __restrict__ VTl)
{
    gemm_core<1>(vh, vl, Wvh, nullptr, bv, nullptr, VTh, VTl,
                 CC, CC, blockIdx.y * BM, blockIdx.x * BN, CC, 1.0f, 0, 1);
}

// ---------------------------------------------------------------------------
// General GEMM kernel (scores MODE0 / PV MODE2 / final MODE1)
// ---------------------------------------------------------------------------
template<int MODE>
__global__ __launch_bounds__(NTH, 2)
void gemm_gen(const h16* __restrict__ Ah, const h16* __restrict__ Al,
              const h16* __restrict__ Bh, const h16* __restrict__ Bl,
              const float* __restrict__ bias,
              float* __restrict__ Cf, h16* __restrict__ Ch, h16* __restrict__ Cl,
              int N, int K,
              size_t sA, size_t sB, size_t sC,
              float alpha, int causal, int kvlim, int transC)
{
    const int bx = blockIdx.x, by = blockIdx.y, bz = blockIdx.z;
    if (causal && bx > by) return;
    const int Keff = kvlim ? (by + 1) * BM : K;
    gemm_core<MODE>(Ah + (size_t)bz * sA, Al ? Al + (size_t)bz * sA : nullptr,
                    Bh + (size_t)bz * sB, Bl ? Bl + (size_t)bz * sB : nullptr, bias,
                    Cf ? Cf + (size_t)bz * sC : nullptr,
                    Ch ? Ch + (size_t)bz * sC : nullptr,
                    Cl ? Cl + (size_t)bz * sC : nullptr,
                    N, K, by * BM, bx * BN, Keff,
                    alpha, causal && bx == by, transC);
}

// ---------------------------------------------------------------------------
// Single-pass row softmax: S fp32 -> single fp16 probabilities.
// ---------------------------------------------------------------------------
__global__ __launch_bounds__(256)
void softmax_kernel(const float* __restrict__ S, h16* __restrict__ Ph)
{
    const int row = blockIdx.x;
    const int b   = blockIdx.y;
    const size_t base = ((size_t)b * TT + row) * TT;
    const float* Sr = S + base;
    const int ncols = ((row >> 7) + 1) << 7;
    const int t = threadIdx.x;
    const int lane = t & 31, wp = t >> 5;

    __shared__ float red[8];

    float vals[8];
    float mx = NEG_INF;
#pragma unroll
    for (int i = 0; i < 8; i++) {
        const int c = t + i * 256;
        vals[i] = (c < ncols) ? Sr[c] : NEG_INF;
        mx = fmaxf(mx, vals[i]);
    }
#pragma unroll
    for (int s = 16; s > 0; s >>= 1) mx = fmaxf(mx, __shfl_xor_sync(~0u, mx, s));
    if (lane == 0) red[wp] = mx;
    __syncthreads();
    mx = red[0];
#pragma unroll
    for (int i = 1; i < 8; i++) mx = fmaxf(mx, red[i]);

    float sum = 0.0f;
#pragma unroll
    for (int i = 0; i < 8; i++) {
        vals[i] = __expf(vals[i] - mx);
        sum += vals[i];
    }
#pragma unroll
    for (int s = 16; s > 0; s >>= 1) sum += __shfl_xor_sync(~0u, sum, s);
    __syncthreads();
    if (lane == 0) red[wp] = sum;
    __syncthreads();
    sum = 0.0f;
#pragma unroll
    for (int i = 0; i < 8; i++) sum += red[i];
    const float inv = 1.0f / sum;

#pragma unroll
    for (int i = 0; i < 8; i++) {
        const int c = t + i * 256;
        if (c < ncols) Ph[base + c] = __float2half_rn(vals[i] * inv);
    }
}

// ---------------------------------------------------------------------------
extern "C" void kernel_launch(void* const* d_in, const int* in_sizes, int n_in,
                              void* d_out, int out_size)
{
    const float* q   = (const float*)d_in[0];
    const float* k   = (const float*)d_in[1];
    const float* v   = (const float*)d_in[2];
    const float* Wq  = (const float*)d_in[3];
    const float* bq  = (const float*)d_in[4];
    const float* Wk  = (const float*)d_in[5];
    const float* bk  = (const float*)d_in[6];
    const float* Wv  = (const float*)d_in[7];
    const float* bv  = (const float*)d_in[8];
    const float* Wff = (const float*)d_in[9];
    const float* bff = (const float*)d_in[10];
    float* out = (float*)d_out;

#define SYM(T, p, g) T p; cudaGetSymbolAddress((void**)&p, g)
    SYM(h16*, qh, g_qh);   SYM(h16*, ql, g_ql);
    SYM(h16*, kh, g_kh);   SYM(h16*, kl, g_kl);
    SYM(h16*, vh, g_vh);   SYM(h16*, vl, g_vl);
    SYM(h16*, Wqh, g_Wqh); SYM(h16*, Wql, g_Wql);
    SYM(h16*, Wkh, g_Wkh); SYM(h16*, Wkl, g_Wkl);
    SYM(h16*, Wvh, g_Wvh); SYM(h16*, Wvl, g_Wvl);
    SYM(h16*, Wfh, g_Wfh); SYM(h16*, Wfl, g_Wfl);
    SYM(h16*, Qh, g_Qh);   SYM(h16*, Ql, g_Ql);
    SYM(h16*, Kh, g_Kh);   SYM(h16*, Kl, g_Kl);
    SYM(h16*, VTh, g_VTh); SYM(h16*, VTl, g_VTl);
    SYM(h16*, Oh, g_Oh);   SYM(h16*, Ol, g_Ol);
    SYM(h16*, Ph, g_Ph);
    SYM(float*, S, g_S);
#undef SYM

    cudaFuncSetAttribute(gemm_qk,     cudaFuncAttributeMaxDynamicSharedMemorySize, SMEM_BYTES);
    cudaFuncSetAttribute(gemm_v,      cudaFuncAttributeMaxDynamicSharedMemorySize, SMEM_BYTES);
    cudaFuncSetAttribute(gemm_gen<0>, cudaFuncAttributeMaxDynamicSharedMemorySize, SMEM_BYTES);
    cudaFuncSetAttribute(gemm_gen<1>, cudaFuncAttributeMaxDynamicSharedMemorySize, SMEM_BYTES);
    cudaFuncSetAttribute(gemm_gen<2>, cudaFuncAttributeMaxDynamicSharedMemorySize, SMEM_BYTES);

    const int M = BATCH * TT;          // 8192
    const int NQ4 = (M * CC) / 4;
    const int NW4 = (CC * CC) / 4;

    // 0) one fused split prepass
    split_all<<<dim3((NQ4 + 255)/256, 7), 256>>>(
        q, k, v, Wq, Wk, Wv, Wff,
        qh, ql, kh, kl, vh, vl,
        Wqh, Wql, Wkh, Wkl, Wvh, Wvl, Wfh, Wfl, NQ4, NW4);

    const dim3 blk(NTH);

    // 1) Q/K projections (3-term, fused) and V projection (2-term, transposed)
    gemm_qk<<<dim3(CC/BN, M/BM, 2), blk, SMEM_BYTES>>>(
        qh, ql, kh, kl, Wqh, Wql, Wkh, Wkl, bq, bk, Qh, Ql, Kh, Kl);
    gemm_v<<<dim3(CC/BN, M/BM, 1), blk, SMEM_BYTES>>>(
        vh, vl, Wvh, bv, VTh, VTl);

    // 2) Scores -> fp32 S (3-term, causal lower-tri blocks only)
    gemm_gen<0><<<dim3(TT/BN, TT/BM, BATCH), blk, SMEM_BYTES>>>(
        Qh, Ql, Kh, Kl, nullptr, S, nullptr, nullptr,
        TT, CC, (size_t)TT*CC, (size_t)TT*CC, (size_t)TT*TT,
        1.0f/32.0f, 1, 0, 0);

    // 3) softmax -> single fp16 probabilities
    softmax_kernel<<<dim3(TT, BATCH), dim3(256)>>>(S, Ph);

    // 4) O = P @ V (2-term B-split, causal K-limit) -> split O   [launch 5: profiled]
    gemm_gen<2><<<dim3(CC/BN, TT/BM, BATCH), blk, SMEM_BYTES>>>(
        Ph, nullptr, VTh, VTl, nullptr, nullptr, Oh, Ol,
        CC, TT, (size_t)TT*TT, (size_t)CC*TT, (size_t)TT*CC,
        1.0f, 0, 1, 0);

    // 5) final projection (2-term A-split) -> fp32 out
    gemm_gen<1><<<dim3(CC/BN, M/BM, 1), blk, SMEM_BYTES>>>(
        Oh, Ol, Wfh, nullptr, bff, out, nullptr, nullptr,
        CC, CC, 0, 0, 0, 1.0f, 0, 0, 0);
}

// round 16
// speedup vs baseline: 3.4047x; 1.1694x over previous
#include <cuda_runtime.h>
#include <cuda_fp16.h>
#include <cstdint>
#include <cstddef>

#define BATCH 4
#define TT    2048
#define CC    1024
#define NEG_INF (__int_as_float(0xff800000))

#define BM 128
#define BN 128
#define BK 32
#define NTH 256

// SMEM: up to 4 fp16 tiles of 128 rows x 40 (32 + 8 pad) per stage, 2 stages
#define ROWSTR 40
#define TILE_E (128 * ROWSTR)
#define OFF_AH 0
#define OFF_AL (1 * TILE_E)
#define OFF_BH (2 * TILE_E)
#define OFF_BL (3 * TILE_E)
#define STAGE_E (4 * TILE_E)               // 20480 elems = 40960 B
#define SMEM_BYTES (2 * STAGE_E * 2)       // 81920 B

typedef __half h16;

// MODE 1: 2-term A-split (A hi/lo, B single; AhB + AlB)
// MODE 2: 2-term B-split (A single, B hi/lo; ABh + ABl)

// ---------------- scratch (device globals; allocation-free rule) ------------
__device__ h16 g_qh[(size_t)BATCH*TT*CC],  g_ql[(size_t)BATCH*TT*CC];
__device__ h16 g_kh[(size_t)BATCH*TT*CC],  g_kl[(size_t)BATCH*TT*CC];
__device__ h16 g_vh[(size_t)BATCH*TT*CC],  g_vl[(size_t)BATCH*TT*CC];
__device__ h16 g_Wqh[CC*CC], g_Wkh[CC*CC], g_Wvh[CC*CC], g_Wfh[CC*CC];
__device__ h16 g_Qh[(size_t)BATCH*TT*CC],  g_Ql[(size_t)BATCH*TT*CC];
__device__ h16 g_Kh[(size_t)BATCH*TT*CC];
__device__ h16 g_VTh[(size_t)BATCH*CC*TT], g_VTl[(size_t)BATCH*CC*TT];
__device__ h16 g_Oh[(size_t)BATCH*TT*CC],  g_Ol[(size_t)BATCH*TT*CC];
__device__ h16 g_Ph[(size_t)BATCH*TT*TT];
__device__ float g_S[(size_t)BATCH*TT*TT];

// ---------------------------------------------------------------------------
__device__ __forceinline__ void mma_f16(float* d, const uint32_t* a, uint32_t b0, uint32_t b1) {
    asm volatile(
        "mma.sync.aligned.m16n8k16.row.col.f32.f16.f16.f32 "
        "{%0,%1,%2,%3},{%4,%5,%6,%7},{%8,%9},{%0,%1,%2,%3};\n"
        : "+f"(d[0]), "+f"(d[1]), "+f"(d[2]), "+f"(d[3])
        : "r"(a[0]), "r"(a[1]), "r"(a[2]), "r"(a[3]), "r"(b0), "r"(b1));
}

#define LDSM4(r, addr)                                                           \
    asm volatile("ldmatrix.sync.aligned.m8n8.x4.shared.b16 {%0,%1,%2,%3}, [%4];" \
        : "=r"((r)[0]), "=r"((r)[1]), "=r"((r)[2]), "=r"((r)[3]) : "r"(addr))

#define CP16(dst_u32, src_ptr) \
    asm volatile("cp.async.cg.shared.global [%0], [%1], 16;" :: "r"(dst_u32), "l"(src_ptr))
#define CP_COMMIT() asm volatile("cp.async.commit_group;")
#define CP_WAIT1()  asm volatile("cp.async.wait_group 1;")

__device__ __forceinline__ void split1(float f, h16& h, h16& l) {
    h = __float2half_rn(f);
    l = __float2half_rn(f - __half2float(h));
}

// ---------------------------------------------------------------------------
// One fused split prepass: q/k/v -> fp16 hi/lo, weights -> fp16 hi only.
// ---------------------------------------------------------------------------
__global__ __launch_bounds__(256)
void split_all(const float* __restrict__ q, const float* __restrict__ k,
               const float* __restrict__ v, const float* __restrict__ Wq,
               const float* __restrict__ Wk, const float* __restrict__ Wv,
               const float* __restrict__ Wf,
               h16* __restrict__ qh, h16* __restrict__ ql,
               h16* __restrict__ kh, h16* __restrict__ kl,
               h16* __restrict__ vh, h16* __restrict__ vl,
               h16* __restrict__ Wqh, h16* __restrict__ Wkh,
               h16* __restrict__ Wvh, h16* __restrict__ Wfh,
               int nbig4, int nsmall4)
{
    const int s = blockIdx.y;
    const int n4 = (s < 3) ? nbig4 : nsmall4;
    const int i = blockIdx.x * 256 + threadIdx.x;
    if (i >= n4) return;
    if (s < 3) {
        const float* src = (s == 0) ? q : (s == 1) ? k : v;
        h16* hi = (s == 0) ? qh : (s == 1) ? kh : vh;
        h16* lo = (s == 0) ? ql : (s == 1) ? kl : vl;
        float4 f = ((const float4*)src)[i];
        h16 h0,l0,h1,l1,h2,l2,h3,l3;
        split1(f.x,h0,l0); split1(f.y,h1,l1); split1(f.z,h2,l2); split1(f.w,h3,l3);
        ((__half2*)hi)[2*i]   = __half2{h0,h1};
        ((__half2*)hi)[2*i+1] = __half2{h2,h3};
        ((__half2*)lo)[2*i]   = __half2{l0,l1};
        ((__half2*)lo)[2*i+1] = __half2{l2,l3};
    } else {
        const float* src = (s == 3) ? Wq : (s == 4) ? Wk : (s == 5) ? Wv : Wf;
        h16* hi = (s == 3) ? Wqh : (s == 4) ? Wkh : (s == 5) ? Wvh : Wfh;
        float4 f = ((const float4*)src)[i];
        ((__half2*)hi)[2*i]   = __half2{__float2half_rn(f.x), __float2half_rn(f.y)};
        ((__half2*)hi)[2*i+1] = __half2{__float2half_rn(f.z), __float2half_rn(f.w)};
    }
}

// ---------------------------------------------------------------------------
// Core split-fp16 mma.sync GEMM-NT tile, MODE-templated (2-term only).
// Output: Cf fp32, else Ch (+ Cl if non-null) fp16, optional transC.
// ---------------------------------------------------------------------------
template<int MODE>
__device__ __forceinline__ void gemm_core(
    const h16* __restrict__ Ah, const h16* __restrict__ Al,
    const h16* __restrict__ Bh, const h16* __restrict__ Bl,
    const float* __restrict__ bias,
    float* __restrict__ Cf, h16* __restrict__ Ch, h16* __restrict__ Cl,
    int N, int K, int m0, int n0, int Keff,
    float alpha, int diag, int transC)
{
    const int nch = Keff / BK;

    extern __shared__ h16 sm[];
    const uint32_t smb = (uint32_t)__cvta_generic_to_shared(sm);

    const int t = threadIdx.x, w = t >> 5, lane = t & 31;
    const int qr = lane >> 2, qc = (lane & 3) * 2;
    const int mb = (w & 1) * 64, nb = (w >> 1) * 32;

    // cp.async geometry: 2 16B-chunks per tile per thread (same row, adjacent cols)
    const int r0 = (t * 2) >> 2, c0 = (t * 2) & 3;

    const h16* pAh = Ah + (size_t)(m0 + r0) * K + c0 * 8;
    const h16* pAl = Al + (size_t)(m0 + r0) * K + c0 * 8;
    const h16* pBh = Bh + (size_t)(n0 + r0) * K + c0 * 8;
    const h16* pBl = Bl + (size_t)(n0 + r0) * K + c0 * 8;
    const uint32_t dA0 = (uint32_t)((r0 * ROWSTR + c0 * 8) * 2);
    const uint32_t dA1 = dA0 + 16;

    // ldmatrix per-lane byte offsets
    uint32_t offA[4];
#pragma unroll
    for (int ii = 0; ii < 4; ii++)
        offA[ii] = (uint32_t)(((mb + ii * 16 + (lane & 15)) * ROWSTR + (lane >> 4) * 8) * 2);
    uint32_t offB[2];
#pragma unroll
    for (int jp = 0; jp < 2; jp++)
        offB[jp] = (uint32_t)(((nb + jp * 16 + ((lane >> 4) * 8) + (lane & 7)) * ROWSTR
                               + ((lane >> 3) & 1) * 8) * 2);

    float acc[4][4][4] = {};

    auto issue = [&](int i) {
        const int k0 = i * BK;
        const uint32_t stg = smb + (uint32_t)((i & 1) * STAGE_E * 2);
        CP16(stg + OFF_AH*2 + dA0, pAh + k0);
        CP16(stg + OFF_AH*2 + dA1, pAh + k0 + 8);
        if (MODE != 2) {
            CP16(stg + OFF_AL*2 + dA0, pAl + k0);
            CP16(stg + OFF_AL*2 + dA1, pAl + k0 + 8);
        }
        CP16(stg + OFF_BH*2 + dA0, pBh + k0);
        CP16(stg + OFF_BH*2 + dA1, pBh + k0 + 8);
        if (MODE != 1) {
            CP16(stg + OFF_BL*2 + dA0, pBl + k0);
            CP16(stg + OFF_BL*2 + dA1, pBl + k0 + 8);
        }
        CP_COMMIT();
    };

    issue(0);
    if (nch > 1) issue(1);

#define BH0(j) bh[(j) >> 1][((j) & 1) * 2]
#define BH1(j) bh[(j) >> 1][((j) & 1) * 2 + 1]
#define BL0(j) bl[(j) >> 1][((j) & 1) * 2]
#define BL1(j) bl[(j) >> 1][((j) & 1) * 2 + 1]

    for (int i = 0; i < nch; i++) {
        CP_WAIT1();
        __syncthreads();
        const uint32_t stg = smb + (uint32_t)((i & 1) * STAGE_E * 2);
#pragma unroll
        for (int kk = 0; kk < BK; kk += 16) {
            const uint32_t kkb = (uint32_t)(kk * 2);
            uint32_t bh[2][4], bl[2][4];
            LDSM4(bh[0], stg + OFF_BH*2 + offB[0] + kkb);
            LDSM4(bh[1], stg + OFF_BH*2 + offB[1] + kkb);
            if (MODE != 1) {
                LDSM4(bl[0], stg + OFF_BL*2 + offB[0] + kkb);
                LDSM4(bl[1], stg + OFF_BL*2 + offB[1] + kkb);
            }
#pragma unroll
            for (int ip = 0; ip < 2; ip++) {
                const int i0 = ip * 2, i1 = ip * 2 + 1;
                uint32_t ah0[4], al0[4], ah1[4], al1[4];
                LDSM4(ah0, stg + OFF_AH*2 + offA[i0] + kkb);
                LDSM4(ah1, stg + OFF_AH*2 + offA[i1] + kkb);
                if (MODE != 2) {
                    LDSM4(al0, stg + OFF_AL*2 + offA[i0] + kkb);
                    LDSM4(al1, stg + OFF_AL*2 + offA[i1] + kkb);
                }
#pragma unroll
                for (int j = 0; j < 4; j++) mma_f16(acc[i0][j], ah0, BH0(j), BH1(j));
#pragma unroll
                for (int j = 0; j < 4; j++) mma_f16(acc[i1][j], ah1, BH0(j), BH1(j));
                if (MODE != 1) {
#pragma unroll
                    for (int j = 0; j < 4; j++) mma_f16(acc[i0][j], ah0, BL0(j), BL1(j));
#pragma unroll
                    for (int j = 0; j < 4; j++) mma_f16(acc[i1][j], ah1, BL0(j), BL1(j));
                }
                if (MODE != 2) {
#pragma unroll
                    for (int j = 0; j < 4; j++) mma_f16(acc[i0][j], al0, BH0(j), BH1(j));
#pragma unroll
                    for (int j = 0; j < 4; j++) mma_f16(acc[i1][j], al1, BH0(j), BH1(j));
                }
            }
        }
        __syncthreads();
        if (i + 2 < nch) issue(i + 2);
    }

#undef BH0
#undef BH1
#undef BL0
#undef BL1

    // ---- epilogue
#pragma unroll
    for (int ii = 0; ii < 4; ii++) {
#pragma unroll
        for (int j = 0; j < 4; j++) {
            const int rA = m0 + mb + ii * 16 + qr;
            const int rB = rA + 8;
            const int cb = n0 + nb + j * 8 + qc;
            float v00 = acc[ii][j][0] * alpha, v01 = acc[ii][j][1] * alpha;
            float v10 = acc[ii][j][2] * alpha, v11 = acc[ii][j][3] * alpha;
            if (bias) {
                const float b0 = bias[cb], b1 = bias[cb + 1];
                v00 += b0; v01 += b1; v10 += b0; v11 += b1;
            }
            if (diag) {
                if (cb     > rA) v00 = NEG_INF;
                if (cb + 1 > rA) v01 = NEG_INF;
                if (cb     > rB) v10 = NEG_INF;
                if (cb + 1 > rB) v11 = NEG_INF;
            }
            if (Cf) {
                *(float2*)&Cf[(size_t)rA * N + cb] = make_float2(v00, v01);
                *(float2*)&Cf[(size_t)rB * N + cb] = make_float2(v10, v11);
            } else if (transC) {
                const size_t bo = (size_t)(rA >> 11) * ((size_t)CC * TT);
                const int mA = rA & (TT - 1), mB = rB & (TT - 1);
                h16 h, l;
                split1(v00, h, l); Ch[bo + (size_t)cb*TT + mA] = h; Cl[bo + (size_t)cb*TT + mA] = l;
                split1(v01, h, l); Ch[bo + (size_t)(cb+1)*TT + mA] = h; Cl[bo + (size_t)(cb+1)*TT + mA] = l;
                split1(v10, h, l); Ch[bo + (size_t)cb*TT + mB] = h; Cl[bo + (size_t)cb*TT + mB] = l;
                split1(v11, h, l); Ch[bo + (size_t)(cb+1)*TT + mB] = h; Cl[bo + (size_t)(cb+1)*TT + mB] = l;
            } else {
                h16 h0,l0,h1,l1;
                split1(v00,h0,l0); split1(v01,h1,l1);
                *(__half2*)&Ch[(size_t)rA*N + cb] = __half2{h0,h1};
                if (Cl) *(__half2*)&Cl[(size_t)rA*N + cb] = __half2{l0,l1};
                split1(v10,h0,l0); split1(v11,h1,l1);
                *(__half2*)&Ch[(size_t)rB*N + cb] = __half2{h0,h1};
                if (Cl) *(__half2*)&Cl[(size_t)rB*N + cb] = __half2{l0,l1};
            }
        }
    }
}

// ---------------------------------------------------------------------------
// Fused Q/K/V projections (all MODE1): z selects problem.
//  z=0: Q -> hi/lo split   z=1: K -> hi only   z=2: V -> hi/lo transposed
// ---------------------------------------------------------------------------
__global__ __launch_bounds__(NTH, 2)
void gemm_qkv(const h16* __restrict__ qh, const h16* __restrict__ ql,
              const h16* __restrict__ kh, const h16* __restrict__ kl,
              const h16* __restrict__ vh, const h16* __restrict__ vl,
              const h16* __restrict__ Wqh, const h16* __restrict__ Wkh,
              const h16* __restrict__ Wvh,
              const float* __restrict__ bq, const float* __restrict__ bk,
              const float* __restrict__ bv,
              h16* __restrict__ Qh, h16* __restrict__ Ql,
              h16* __restrict__ Kh,
              h16* __restrict__ VTh, h16* __restrict__ VTl)
{
    const int z = blockIdx.z;
    const h16 *Ah, *Al, *Bh;
    const float* bias;
    h16 *Ch, *Cl;
    int transC = 0;
    if (z == 0)      { Ah=qh; Al=ql; Bh=Wqh; bias=bq; Ch=Qh;  Cl=Ql; }
    else if (z == 1) { Ah=kh; Al=kl; Bh=Wkh; bias=bk; Ch=Kh;  Cl=nullptr; }
    else             { Ah=vh; Al=vl; Bh=Wvh; bias=bv; Ch=VTh; Cl=VTl; transC=1; }
    gemm_core<1>(Ah, Al, Bh, nullptr, bias, nullptr, Ch, Cl,
                 CC, CC, blockIdx.y * BM, blockIdx.x * BN, CC, 1.0f, 0, transC);
}

// ---------------------------------------------------------------------------
// General GEMM kernel (scores MODE1 / PV MODE2 / final MODE1)
// ---------------------------------------------------------------------------
template<int MODE>
__global__ __launch_bounds__(NTH, 2)
void gemm_gen(const h16* __restrict__ Ah, const h16* __restrict__ Al,
              const h16* __restrict__ Bh, const h16* __restrict__ Bl,
              const float* __restrict__ bias,
              float* __restrict__ Cf, h16* __restrict__ Ch, h16* __restrict__ Cl,
              int N, int K,
              size_t sA, size_t sB, size_t sC,
              float alpha, int causal, int kvlim, int transC)
{
    const int bx = blockIdx.x, by = blockIdx.y, bz = blockIdx.z;
    if (causal && bx > by) return;
    const int Keff = kvlim ? (by + 1) * BM : K;
    gemm_core<MODE>(Ah + (size_t)bz * sA, Al ? Al + (size_t)bz * sA : nullptr,
                    Bh + (size_t)bz * sB, Bl ? Bl + (size_t)bz * sB : nullptr, bias,
                    Cf ? Cf + (size_t)bz * sC : nullptr,
                    Ch ? Ch + (size_t)bz * sC : nullptr,
                    Cl ? Cl + (size_t)bz * sC : nullptr,
                    N, K, by * BM, bx * BN, Keff,
                    alpha, causal && bx == by, transC);
}

// ---------------------------------------------------------------------------
// Single-pass row softmax: S fp32 -> single fp16 probabilities.
// ---------------------------------------------------------------------------
__global__ __launch_bounds__(256)
void softmax_kernel(const float* __restrict__ S, h16* __restrict__ Ph)
{
    const int row = blockIdx.x;
    const int b   = blockIdx.y;
    const size_t base = ((size_t)b * TT + row) * TT;
    const float* Sr = S + base;
    const int ncols = ((row >> 7) + 1) << 7;
    const int t = threadIdx.x;
    const int lane = t & 31, wp = t >> 5;

    __shared__ float red[8];

    float vals[8];
    float mx = NEG_INF;
#pragma unroll
    for (int i = 0; i < 8; i++) {
        const int c = t + i * 256;
        vals[i] = (c < ncols) ? Sr[c] : NEG_INF;
        mx = fmaxf(mx, vals[i]);
    }
#pragma unroll
    for (int s = 16; s > 0; s >>= 1) mx = fmaxf(mx, __shfl_xor_sync(~0u, mx, s));
    if (lane == 0) red[wp] = mx;
    __syncthreads();
    mx = red[0];
#pragma unroll
    for (int i = 1; i < 8; i++) mx = fmaxf(mx, red[i]);

    float sum = 0.0f;
#pragma unroll
    for (int i = 0; i < 8; i++) {
        vals[i] = __expf(vals[i] - mx);
        sum += vals[i];
    }
#pragma unroll
    for (int s = 16; s > 0; s >>= 1) sum += __shfl_xor_sync(~0u, sum, s);
    __syncthreads();
    if (lane == 0) red[wp] = sum;
    __syncthreads();
    sum = 0.0f;
#pragma unroll
    for (int i = 0; i < 8; i++) sum += red[i];
    const float inv = 1.0f / sum;

#pragma unroll
    for (int i = 0; i < 8; i++) {
        const int c = t + i * 256;
        if (c < ncols) Ph[base + c] = __float2half_rn(vals[i] * inv);
    }
}

// ---------------------------------------------------------------------------
extern "C" void kernel_launch(void* const* d_in, const int* in_sizes, int n_in,
                              void* d_out, int out_size)
{
    const float* q   = (const float*)d_in[0];
    const float* k   = (const float*)d_in[1];
    const float* v   = (const float*)d_in[2];
    const float* Wq  = (const float*)d_in[3];
    const float* bq  = (const float*)d_in[4];
    const float* Wk  = (const float*)d_in[5];
    const float* bk  = (const float*)d_in[6];
    const float* Wv  = (const float*)d_in[7];
    const float* bv  = (const float*)d_in[8];
    const float* Wff = (const float*)d_in[9];
    const float* bff = (const float*)d_in[10];
    float* out = (float*)d_out;

#define SYM(T, p, g) T p; cudaGetSymbolAddress((void**)&p, g)
    SYM(h16*, qh, g_qh);   SYM(h16*, ql, g_ql);
    SYM(h16*, kh, g_kh);   SYM(h16*, kl, g_kl);
    SYM(h16*, vh, g_vh);   SYM(h16*, vl, g_vl);
    SYM(h16*, Wqh, g_Wqh); SYM(h16*, Wkh, g_Wkh);
    SYM(h16*, Wvh, g_Wvh); SYM(h16*, Wfh, g_Wfh);
    SYM(h16*, Qh, g_Qh);   SYM(h16*, Ql, g_Ql);
    SYM(h16*, Kh, g_Kh);
    SYM(h16*, VTh, g_VTh); SYM(h16*, VTl, g_VTl);
    SYM(h16*, Oh, g_Oh);   SYM(h16*, Ol, g_Ol);
    SYM(h16*, Ph, g_Ph);
    SYM(float*, S, g_S);
#undef SYM

    cudaFuncSetAttribute(gemm_qkv,    cudaFuncAttributeMaxDynamicSharedMemorySize, SMEM_BYTES);
    cudaFuncSetAttribute(gemm_gen<1>, cudaFuncAttributeMaxDynamicSharedMemorySize, SMEM_BYTES);
    cudaFuncSetAttribute(gemm_gen<2>, cudaFuncAttributeMaxDynamicSharedMemorySize, SMEM_BYTES);

    const int M = BATCH * TT;          // 8192
    const int NQ4 = (M * CC) / 4;
    const int NW4 = (CC * CC) / 4;

    // 0) one fused split prepass (inputs hi/lo, weights hi-only)
    split_all<<<dim3((NQ4 + 255)/256, 7), 256>>>(
        q, k, v, Wq, Wk, Wv, Wff,
        qh, ql, kh, kl, vh, vl,
        Wqh, Wkh, Wvh, Wfh, NQ4, NW4);

    const dim3 blk(NTH);

    // 1) fused Q/K/V projections (all 2-term MODE1)
    gemm_qkv<<<dim3(CC/BN, M/BM, 3), blk, SMEM_BYTES>>>(
        qh, ql, kh, kl, vh, vl, Wqh, Wkh, Wvh,
        bq, bk, bv, Qh, Ql, Kh, VTh, VTl);

    // 2) Scores -> fp32 S (2-term MODE1: Q split x K single, causal blocks)
    gemm_gen<1><<<dim3(TT/BN, TT/BM, BATCH), blk, SMEM_BYTES>>>(
        Qh, Ql, Kh, nullptr, nullptr, S, nullptr, nullptr,
        TT, CC, (size_t)TT*CC, (size_t)TT*CC, (size_t)TT*TT,
        1.0f/32.0f, 1, 0, 0);

    // 3) softmax -> single fp16 probabilities
    softmax_kernel<<<dim3(TT, BATCH), dim3(256)>>>(S, Ph);

    // 4) O = P @ V (2-term MODE2, causal K-limit) -> split O
    gemm_gen<2><<<dim3(CC/BN, TT/BM, BATCH), blk, SMEM_BYTES>>>(
        Ph, nullptr, VTh, VTl, nullptr, nullptr, Oh, Ol,
        CC, TT, (size_t)TT*TT, (size_t)CC*TT, (size_t)TT*CC,
        1.0f, 0, 1, 0);

    // 5) final projection (2-term MODE1) -> fp32 out
    gemm_gen<1><<<dim3(CC/BN, M/BM, 1), blk, SMEM_BYTES>>>(
        Oh, Ol, Wfh, nullptr, bff, out, nullptr, nullptr,
        CC, CC, 0, 0, 0, 1.0f, 0, 0, 0);
}

// round 17
// speedup vs baseline: 4.3213x; 1.2692x over previous
#include <cuda_runtime.h>
#include <cuda_fp16.h>
#include <cstdint>
#include <cstddef>

#define BATCH 4
#define TT    2048
#define CC    1024
#define NEG_INF (__int_as_float(0xff800000))

#define BM 128
#define BN 128
#define BK 32
#define NTH 256

// SMEM: up to 4 fp16 tiles of 128 rows x 40 (32 + 8 pad) per stage, 2 stages
#define ROWSTR 40
#define TILE_E (128 * ROWSTR)
#define OFF_AH 0
#define OFF_AL (1 * TILE_E)
#define OFF_BH (2 * TILE_E)
#define OFF_BL (3 * TILE_E)
#define STAGE_E (4 * TILE_E)               // 20480 elems = 40960 B
#define SMEM_BYTES (2 * STAGE_E * 2)       // 81920 B

typedef __half h16;

// MODE 1: 2-term A-split (A hi/lo, B single; AhB + AlB)
// MODE 2: 2-term B-split (A single, B hi/lo; ABh + ABl)
// MODE 3: 1-term single  (A single,  B single; AB)

// ---------------- scratch (device globals; allocation-free rule) ------------
__device__ h16 g_qh[(size_t)BATCH*TT*CC],  g_ql[(size_t)BATCH*TT*CC];
__device__ h16 g_kh[(size_t)BATCH*TT*CC],  g_kl[(size_t)BATCH*TT*CC];
__device__ h16 g_vh[(size_t)BATCH*TT*CC];
__device__ h16 g_Wqh[CC*CC], g_Wkh[CC*CC], g_Wvh[CC*CC], g_Wfh[CC*CC];
__device__ h16 g_Qh[(size_t)BATCH*TT*CC],  g_Ql[(size_t)BATCH*TT*CC];
__device__ h16 g_Kh[(size_t)BATCH*TT*CC];
__device__ h16 g_VTh[(size_t)BATCH*CC*TT];
__device__ h16 g_Oh[(size_t)BATCH*TT*CC];
__device__ h16 g_Ph[(size_t)BATCH*TT*TT];
__device__ float g_S[(size_t)BATCH*TT*TT];

// ---------------------------------------------------------------------------
__device__ __forceinline__ void mma_f16(float* d, const uint32_t* a, uint32_t b0, uint32_t b1) {
    asm volatile(
        "mma.sync.aligned.m16n8k16.row.col.f32.f16.f16.f32 "
        "{%0,%1,%2,%3},{%4,%5,%6,%7},{%8,%9},{%0,%1,%2,%3};\n"
        : "+f"(d[0]), "+f"(d[1]), "+f"(d[2]), "+f"(d[3])
        : "r"(a[0]), "r"(a[1]), "r"(a[2]), "r"(a[3]), "r"(b0), "r"(b1));
}

#define LDSM4(r, addr)                                                           \
    asm volatile("ldmatrix.sync.aligned.m8n8.x4.shared.b16 {%0,%1,%2,%3}, [%4];" \
        : "=r"((r)[0]), "=r"((r)[1]), "=r"((r)[2]), "=r"((r)[3]) : "r"(addr))

#define CP16(dst_u32, src_ptr) \
    asm volatile("cp.async.cg.shared.global [%0], [%1], 16;" :: "r"(dst_u32), "l"(src_ptr))
#define CP_COMMIT() asm volatile("cp.async.commit_group;")
#define CP_WAIT1()  asm volatile("cp.async.wait_group 1;")

__device__ __forceinline__ void split1(float f, h16& h, h16& l) {
    h = __float2half_rn(f);
    l = __float2half_rn(f - __half2float(h));
}

// ---------------------------------------------------------------------------
// One fused split prepass: q/k -> fp16 hi/lo; v + weights -> fp16 hi only.
// ---------------------------------------------------------------------------
__global__ __launch_bounds__(256)
void split_all(const float* __restrict__ q, const float* __restrict__ k,
               const float* __restrict__ v, const float* __restrict__ Wq,
               const float* __restrict__ Wk, const float* __restrict__ Wv,
               const float* __restrict__ Wf,
               h16* __restrict__ qh, h16* __restrict__ ql,
               h16* __restrict__ kh, h16* __restrict__ kl,
               h16* __restrict__ vh,
               h16* __restrict__ Wqh, h16* __restrict__ Wkh,
               h16* __restrict__ Wvh, h16* __restrict__ Wfh,
               int nbig4, int nsmall4)
{
    const int s = blockIdx.y;
    const int n4 = (s < 3) ? nbig4 : nsmall4;
    const int i = blockIdx.x * 256 + threadIdx.x;
    if (i >= n4) return;
    if (s < 2) {
        const float* src = (s == 0) ? q : k;
        h16* hi = (s == 0) ? qh : kh;
        h16* lo = (s == 0) ? ql : kl;
        float4 f = ((const float4*)src)[i];
        h16 h0,l0,h1,l1,h2,l2,h3,l3;
        split1(f.x,h0,l0); split1(f.y,h1,l1); split1(f.z,h2,l2); split1(f.w,h3,l3);
        ((__half2*)hi)[2*i]   = __half2{h0,h1};
        ((__half2*)hi)[2*i+1] = __half2{h2,h3};
        ((__half2*)lo)[2*i]   = __half2{l0,l1};
        ((__half2*)lo)[2*i+1] = __half2{l2,l3};
    } else {
        const float* src = (s == 2) ? v : (s == 3) ? Wq : (s == 4) ? Wk : (s == 5) ? Wv : Wf;
        h16* hi = (s == 2) ? vh : (s == 3) ? Wqh : (s == 4) ? Wkh : (s == 5) ? Wvh : Wfh;
        float4 f = ((const float4*)src)[i];
        ((__half2*)hi)[2*i]   = __half2{__float2half_rn(f.x), __float2half_rn(f.y)};
        ((__half2*)hi)[2*i+1] = __half2{__float2half_rn(f.z), __float2half_rn(f.w)};
    }
}

// ---------------------------------------------------------------------------
// Core split-fp16 mma.sync GEMM-NT tile, MODE-templated.
// ---------------------------------------------------------------------------
template<int MODE>
__device__ __forceinline__ void gemm_core(
    const h16* __restrict__ Ah, const h16* __restrict__ Al,
    const h16* __restrict__ Bh, const h16* __restrict__ Bl,
    const float* __restrict__ bias,
    float* __restrict__ Cf, h16* __restrict__ Ch, h16* __restrict__ Cl,
    int N, int K, int m0, int n0, int Keff,
    float alpha, int diag, int transC)
{
    const int nch = Keff / BK;

    extern __shared__ h16 sm[];
    const uint32_t smb = (uint32_t)__cvta_generic_to_shared(sm);

    const int t = threadIdx.x, w = t >> 5, lane = t & 31;
    const int qr = lane >> 2, qc = (lane & 3) * 2;
    const int mb = (w & 1) * 64, nb = (w >> 1) * 32;

    // cp.async geometry: 2 16B-chunks per tile per thread (same row, adjacent cols)
    const int r0 = (t * 2) >> 2, c0 = (t * 2) & 3;

    const h16* pAh = Ah + (size_t)(m0 + r0) * K + c0 * 8;
    const h16* pAl = (MODE == 1) ? Al + (size_t)(m0 + r0) * K + c0 * 8 : nullptr;
    const h16* pBh = Bh + (size_t)(n0 + r0) * K + c0 * 8;
    const h16* pBl = (MODE == 2) ? Bl + (size_t)(n0 + r0) * K + c0 * 8 : nullptr;
    const uint32_t dA0 = (uint32_t)((r0 * ROWSTR + c0 * 8) * 2);
    const uint32_t dA1 = dA0 + 16;

    // ldmatrix per-lane byte offsets
    uint32_t offA[4];
#pragma unroll
    for (int ii = 0; ii < 4; ii++)
        offA[ii] = (uint32_t)(((mb + ii * 16 + (lane & 15)) * ROWSTR + (lane >> 4) * 8) * 2);
    uint32_t offB[2];
#pragma unroll
    for (int jp = 0; jp < 2; jp++)
        offB[jp] = (uint32_t)(((nb + jp * 16 + ((lane >> 4) * 8) + (lane & 7)) * ROWSTR
                               + ((lane >> 3) & 1) * 8) * 2);

    float acc[4][4][4] = {};

    auto issue = [&](int i) {
        const int k0 = i * BK;
        const uint32_t stg = smb + (uint32_t)((i & 1) * STAGE_E * 2);
        CP16(stg + OFF_AH*2 + dA0, pAh + k0);
        CP16(stg + OFF_AH*2 + dA1, pAh + k0 + 8);
        if (MODE == 1) {
            CP16(stg + OFF_AL*2 + dA0, pAl + k0);
            CP16(stg + OFF_AL*2 + dA1, pAl + k0 + 8);
        }
        CP16(stg + OFF_BH*2 + dA0, pBh + k0);
        CP16(stg + OFF_BH*2 + dA1, pBh + k0 + 8);
        if (MODE == 2) {
            CP16(stg + OFF_BL*2 + dA0, pBl + k0);
            CP16(stg + OFF_BL*2 + dA1, pBl + k0 + 8);
        }
        CP_COMMIT();
    };

    issue(0);
    if (nch > 1) issue(1);

#define BH0(j) bh[(j) >> 1][((j) & 1) * 2]
#define BH1(j) bh[(j) >> 1][((j) & 1) * 2 + 1]
#define BL0(j) bl[(j) >> 1][((j) & 1) * 2]
#define BL1(j) bl[(j) >> 1][((j) & 1) * 2 + 1]

    for (int i = 0; i < nch; i++) {
        CP_WAIT1();
        __syncthreads();
        const uint32_t stg = smb + (uint32_t)((i & 1) * STAGE_E * 2);
#pragma unroll
        for (int kk = 0; kk < BK; kk += 16) {
            const uint32_t kkb = (uint32_t)(kk * 2);
            uint32_t bh[2][4], bl[2][4];
            LDSM4(bh[0], stg + OFF_BH*2 + offB[0] + kkb);
            LDSM4(bh[1], stg + OFF_BH*2 + offB[1] + kkb);
            if (MODE == 2) {
                LDSM4(bl[0], stg + OFF_BL*2 + offB[0] + kkb);
                LDSM4(bl[1], stg + OFF_BL*2 + offB[1] + kkb);
            }
#pragma unroll
            for (int ip = 0; ip < 2; ip++) {
                const int i0 = ip * 2, i1 = ip * 2 + 1;
                uint32_t ah0[4], al0[4], ah1[4], al1[4];
                LDSM4(ah0, stg + OFF_AH*2 + offA[i0] + kkb);
                LDSM4(ah1, stg + OFF_AH*2 + offA[i1] + kkb);
                if (MODE == 1) {
                    LDSM4(al0, stg + OFF_AL*2 + offA[i0] + kkb);
                    LDSM4(al1, stg + OFF_AL*2 + offA[i1] + kkb);
                }
#pragma unroll
                for (int j = 0; j < 4; j++) mma_f16(acc[i0][j], ah0, BH0(j), BH1(j));
#pragma unroll
                for (int j = 0; j < 4; j++) mma_f16(acc[i1][j], ah1, BH0(j), BH1(j));
                if (MODE == 2) {
#pragma unroll
                    for (int j = 0; j < 4; j++) mma_f16(acc[i0][j], ah0, BL0(j), BL1(j));
#pragma unroll
                    for (int j = 0; j < 4; j++) mma_f16(acc[i1][j], ah1, BL0(j), BL1(j));
                }
                if (MODE == 1) {
#pragma unroll
                    for (int j = 0; j < 4; j++) mma_f16(acc[i0][j], al0, BH0(j), BH1(j));
#pragma unroll
                    for (int j = 0; j < 4; j++) mma_f16(acc[i1][j], al1, BH0(j), BH1(j));
                }
            }
        }
        __syncthreads();
        if (i + 2 < nch) issue(i + 2);
    }

#undef BH0
#undef BH1
#undef BL0
#undef BL1

    // ---- epilogue
#pragma unroll
    for (int ii = 0; ii < 4; ii++) {
#pragma unroll
        for (int j = 0; j < 4; j++) {
            const int rA = m0 + mb + ii * 16 + qr;
            const int rB = rA + 8;
            const int cb = n0 + nb + j * 8 + qc;
            float v00 = acc[ii][j][0] * alpha, v01 = acc[ii][j][1] * alpha;
            float v10 = acc[ii][j][2] * alpha, v11 = acc[ii][j][3] * alpha;
            if (bias) {
                const float b0 = bias[cb], b1 = bias[cb + 1];
                v00 += b0; v01 += b1; v10 += b0; v11 += b1;
            }
            if (diag) {
                if (cb     > rA) v00 = NEG_INF;
                if (cb + 1 > rA) v01 = NEG_INF;
                if (cb     > rB) v10 = NEG_INF;
                if (cb + 1 > rB) v11 = NEG_INF;
            }
            if (Cf) {
                *(float2*)&Cf[(size_t)rA * N + cb] = make_float2(v00, v01);
                *(float2*)&Cf[(size_t)rB * N + cb] = make_float2(v10, v11);
            } else if (transC) {
                const size_t bo = (size_t)(rA >> 11) * ((size_t)CC * TT);
                const int mA = rA & (TT - 1), mB = rB & (TT - 1);
                h16 h, l;
                split1(v00, h, l); Ch[bo + (size_t)cb*TT + mA] = h; if (Cl) Cl[bo + (size_t)cb*TT + mA] = l;
                split1(v01, h, l); Ch[bo + (size_t)(cb+1)*TT + mA] = h; if (Cl) Cl[bo + (size_t)(cb+1)*TT + mA] = l;
                split1(v10, h, l); Ch[bo + (size_t)cb*TT + mB] = h; if (Cl) Cl[bo + (size_t)cb*TT + mB] = l;
                split1(v11, h, l); Ch[bo + (size_t)(cb+1)*TT + mB] = h; if (Cl) Cl[bo + (size_t)(cb+1)*TT + mB] = l;
            } else {
                h16 h0,l0,h1,l1;
                split1(v00,h0,l0); split1(v01,h1,l1);
                *(__half2*)&Ch[(size_t)rA*N + cb] = __half2{h0,h1};
                if (Cl) *(__half2*)&Cl[(size_t)rA*N + cb] = __half2{l0,l1};
                split1(v10,h0,l0); split1(v11,h1,l1);
                *(__half2*)&Ch[(size_t)rB*N + cb] = __half2{h0,h1};
                if (Cl) *(__half2*)&Cl[(size_t)rB*N + cb] = __half2{l0,l1};
            }
        }
    }
}

// ---------------------------------------------------------------------------
// Fused Q/K projections (MODE1): z=0 Q (hi/lo out), z=1 K (hi out).
// ---------------------------------------------------------------------------
__global__ __launch_bounds__(NTH, 2)
void gemm_qk(const h16* __restrict__ qh, const h16* __restrict__ ql,
             const h16* __restrict__ kh, const h16* __restrict__ kl,
             const h16* __restrict__ Wqh, const h16* __restrict__ Wkh,
             const float* __restrict__ bq, const float* __restrict__ bk,
             h16* __restrict__ Qh, h16* __restrict__ Ql,
             h16* __restrict__ Kh)
{
    const int z = blockIdx.z;
    gemm_core<1>(z ? kh : qh, z ? kl : ql, z ? Wkh : Wqh, nullptr,
                 z ? bk : bq, nullptr, z ? Kh : Qh, z ? nullptr : Ql,
                 CC, CC, blockIdx.y * BM, blockIdx.x * BN, CC, 1.0f, 0, 0);
}

// ---------------------------------------------------------------------------
// V projection (MODE3 single), transposed hi-only output.
// ---------------------------------------------------------------------------
__global__ __launch_bounds__(NTH, 2)
void gemm_v(const h16* __restrict__ vh, const h16* __restrict__ Wvh,
            const float* __restrict__ bv, h16* __restrict__ VTh)
{
    gemm_core<3>(vh, nullptr, Wvh, nullptr, bv, nullptr, VTh, nullptr,
                 CC, CC, blockIdx.y * BM, blockIdx.x * BN, CC, 1.0f, 0, 1);
}

// ---------------------------------------------------------------------------
// General GEMM kernel (scores MODE1 / PV MODE3 / final MODE3)
// revY: reverse by mapping so heavy kvlim tiles schedule first.
// ---------------------------------------------------------------------------
template<int MODE>
__global__ __launch_bounds__(NTH, 2)
void gemm_gen(const h16* __restrict__ Ah, const h16* __restrict__ Al,
              const h16* __restrict__ Bh, const h16* __restrict__ Bl,
              const float* __restrict__ bias,
              float* __restrict__ Cf, h16* __restrict__ Ch, h16* __restrict__ Cl,
              int N, int K,
              size_t sA, size_t sB, size_t sC,
              float alpha, int causal, int kvlim, int transC)
{
    const int bx = blockIdx.x, bz = blockIdx.z;
    const int by = kvlim ? (gridDim.y - 1 - blockIdx.y) : blockIdx.y;
    if (causal && bx > by) return;
    const int Keff = kvlim ? (by + 1) * BM : K;
    gemm_core<MODE>(Ah + (size_t)bz * sA, Al ? Al + (size_t)bz * sA : nullptr,
                    Bh + (size_t)bz * sB, Bl ? Bl + (size_t)bz * sB : nullptr, bias,
                    Cf ? Cf + (size_t)bz * sC : nullptr,
                    Ch ? Ch + (size_t)bz * sC : nullptr,
                    Cl ? Cl + (size_t)bz * sC : nullptr,
                    N, K, by * BM, bx * BN, Keff,
                    alpha, causal && bx == by, transC);
}

// ---------------------------------------------------------------------------
// Single-pass row softmax: S fp32 -> single fp16 probabilities.
// ---------------------------------------------------------------------------
__global__ __launch_bounds__(256)
void softmax_kernel(const float* __restrict__ S, h16* __restrict__ Ph)
{
    const int row = blockIdx.x;
    const int b   = blockIdx.y;
    const size_t base = ((size_t)b * TT + row) * TT;
    const float* Sr = S + base;
    const int ncols = ((row >> 7) + 1) << 7;
    const int t = threadIdx.x;
    const int lane = t & 31, wp = t >> 5;

    __shared__ float red[8];

    float vals[8];
    float mx = NEG_INF;
#pragma unroll
    for (int i = 0; i < 8; i++) {
        const int c = t + i * 256;
        vals[i] = (c < ncols) ? Sr[c] : NEG_INF;
        mx = fmaxf(mx, vals[i]);
    }
#pragma unroll
    for (int s = 16; s > 0; s >>= 1) mx = fmaxf(mx, __shfl_xor_sync(~0u, mx, s));
    if (lane == 0) red[wp] = mx;
    __syncthreads();
    mx = red[0];
#pragma unroll
    for (int i = 1; i < 8; i++) mx = fmaxf(mx, red[i]);

    float sum = 0.0f;
#pragma unroll
    for (int i = 0; i < 8; i++) {
        vals[i] = __expf(vals[i] - mx);
        sum += vals[i];
    }
#pragma unroll
    for (int s = 16; s > 0; s >>= 1) sum += __shfl_xor_sync(~0u, sum, s);
    __syncthreads();
    if (lane == 0) red[wp] = sum;
    __syncthreads();
    sum = 0.0f;
#pragma unroll
    for (int i = 0; i < 8; i++) sum += red[i];
    const float inv = 1.0f / sum;

#pragma unroll
    for (int i = 0; i < 8; i++) {
        const int c = t + i * 256;
        if (c < ncols) Ph[base + c] = __float2half_rn(vals[i] * inv);
    }
}

// ---------------------------------------------------------------------------
extern "C" void kernel_launch(void* const* d_in, const int* in_sizes, int n_in,
                              void* d_out, int out_size)
{
    const float* q   = (const float*)d_in[0];
    const float* k   = (const float*)d_in[1];
    const float* v   = (const float*)d_in[2];
    const float* Wq  = (const float*)d_in[3];
    const float* bq  = (const float*)d_in[4];
    const float* Wk  = (const float*)d_in[5];
    const float* bk  = (const float*)d_in[6];
    const float* Wv  = (const float*)d_in[7];
    const float* bv  = (const float*)d_in[8];
    const float* Wff = (const float*)d_in[9];
    const float* bff = (const float*)d_in[10];
    float* out = (float*)d_out;

#define SYM(T, p, g) T p; cudaGetSymbolAddress((void**)&p, g)
    SYM(h16*, qh, g_qh);   SYM(h16*, ql, g_ql);
    SYM(h16*, kh, g_kh);   SYM(h16*, kl, g_kl);
    SYM(h16*, vh, g_vh);
    SYM(h16*, Wqh, g_Wqh); SYM(h16*, Wkh, g_Wkh);
    SYM(h16*, Wvh, g_Wvh); SYM(h16*, Wfh, g_Wfh);
    SYM(h16*, Qh, g_Qh);   SYM(h16*, Ql, g_Ql);
    SYM(h16*, Kh, g_Kh);
    SYM(h16*, VTh, g_VTh);
    SYM(h16*, Oh, g_Oh);
    SYM(h16*, Ph, g_Ph);
    SYM(float*, S, g_S);
#undef SYM

    cudaFuncSetAttribute(gemm_qk,     cudaFuncAttributeMaxDynamicSharedMemorySize, SMEM_BYTES);
    cudaFuncSetAttribute(gemm_v,      cudaFuncAttributeMaxDynamicSharedMemorySize, SMEM_BYTES);
    cudaFuncSetAttribute(gemm_gen<1>, cudaFuncAttributeMaxDynamicSharedMemorySize, SMEM_BYTES);
    cudaFuncSetAttribute(gemm_gen<3>, cudaFuncAttributeMaxDynamicSharedMemorySize, SMEM_BYTES);

    const int M = BATCH * TT;          // 8192
    const int NQ4 = (M * CC) / 4;
    const int NW4 = (CC * CC) / 4;

    // 0) one fused split prepass (q/k hi/lo; v + weights hi only)
    split_all<<<dim3((NQ4 + 255)/256, 7), 256>>>(
        q, k, v, Wq, Wk, Wv, Wff,
        qh, ql, kh, kl, vh,
        Wqh, Wkh, Wvh, Wfh, NQ4, NW4);

    const dim3 blk(NTH);

    // 1) Q/K projections (2-term) + V projection (1-term, transposed)
    gemm_qk<<<dim3(CC/BN, M/BM, 2), blk, SMEM_BYTES>>>(
        qh, ql, kh, kl, Wqh, Wkh, bq, bk, Qh, Ql, Kh);
    gemm_v<<<dim3(CC/BN, M/BM, 1), blk, SMEM_BYTES>>>(
        vh, Wvh, bv, VTh);

    // 2) Scores -> fp32 S (2-term: Q split x K single, causal blocks)
    gemm_gen<1><<<dim3(TT/BN, TT/BM, BATCH), blk, SMEM_BYTES>>>(
        Qh, Ql, Kh, nullptr, nullptr, S, nullptr, nullptr,
        TT, CC, (size_t)TT*CC, (size_t)TT*CC, (size_t)TT*TT,
        1.0f/32.0f, 1, 0, 0);

    // 3) softmax -> single fp16 probabilities
    softmax_kernel<<<dim3(TT, BATCH), dim3(256)>>>(S, Ph);

    // 4) O = P @ V (1-term, causal K-limit, heavy tiles first) -> Oh single
    gemm_gen<3><<<dim3(CC/BN, TT/BM, BATCH), blk, SMEM_BYTES>>>(
        Ph, nullptr, VTh, nullptr, nullptr, nullptr, Oh, nullptr,
        CC, TT, (size_t)TT*TT, (size_t)CC*TT, (size_t)TT*CC,
        1.0f, 0, 1, 0);

    // 5) final projection (1-term) -> fp32 out
    gemm_gen<3><<<dim3(CC/BN, M/BM, 1), blk, SMEM_BYTES>>>(
        Oh, nullptr, Wfh, nullptr, bff, out, nullptr, nullptr,
        CC, CC, 0, 0, 0, 1.0f, 0, 0, 0);
}